// round 1
// baseline (speedup 1.0000x reference)
#include <cuda_runtime.h>

#define NN 100000
#define EE 1600000

// ---------------- scratch (static device globals; no allocation) -------------
__device__ float    g_acc[NN * 64];   // clusterGCN sums -> GAT1 unnormalized acc
__device__ float    g_h  [NN * 64];   // relu(clusterGCN out) -> later h2 [N,32]
__device__ float    g_h1 [NN * 64];   // GAT1 h=xW -> later GAT2 acc [N,32]
__device__ float    g_deg [NN];
__device__ float    g_ssrc[NN];
__device__ float    g_sdst[NN];
__device__ unsigned g_menc[NN];
__device__ float    g_mf  [NN];
__device__ float    g_den [NN];

// ---------------- helpers ----------------------------------------------------
__device__ __forceinline__ unsigned fenc(float x) {
    unsigned u = __float_as_uint(x);
    return (u & 0x80000000u) ? ~u : (u | 0x80000000u);
}
__device__ __forceinline__ float fdec(unsigned k) {
    unsigned u = (k & 0x80000000u) ? (k & 0x7fffffffu) : ~k;
    return __uint_as_float(u);
}
__device__ __forceinline__ float lrelu(float z) { return z > 0.f ? z : 0.2f * z; }

__device__ __forceinline__ void red4(float* p, float4 v) {
    asm volatile("red.global.add.v4.f32 [%0], {%1, %2, %3, %4};"
                 :: "l"(p), "f"(v.x), "f"(v.y), "f"(v.z), "f"(v.w) : "memory");
}

__device__ __forceinline__ void fma_row64(float ink, const float* w, float (&acc)[64]) {
    const float4* wr = (const float4*)w;
#pragma unroll
    for (int c4 = 0; c4 < 16; c4++) {
        float4 wv = wr[c4];
        acc[c4*4+0] = fmaf(ink, wv.x, acc[c4*4+0]);
        acc[c4*4+1] = fmaf(ink, wv.y, acc[c4*4+1]);
        acc[c4*4+2] = fmaf(ink, wv.z, acc[c4*4+2]);
        acc[c4*4+3] = fmaf(ink, wv.w, acc[c4*4+3]);
    }
}
__device__ __forceinline__ void fma_row32(float ink, const float* w, float (&acc)[32]) {
    const float4* wr = (const float4*)w;
#pragma unroll
    for (int c4 = 0; c4 < 8; c4++) {
        float4 wv = wr[c4];
        acc[c4*4+0] = fmaf(ink, wv.x, acc[c4*4+0]);
        acc[c4*4+1] = fmaf(ink, wv.y, acc[c4*4+1]);
        acc[c4*4+2] = fmaf(ink, wv.z, acc[c4*4+2]);
        acc[c4*4+3] = fmaf(ink, wv.w, acc[c4*4+3]);
    }
}

// buffer selection by layer (C=64 -> GAT1, C=32 -> GAT2)
template<int C> __device__ __forceinline__ const float* hbuf()   { return (C == 64) ? g_h1 : g_h; }
template<int C> __device__ __forceinline__ float*       accbuf() { return (C == 64) ? g_acc : g_h1; }

// ---------------- kernels ----------------------------------------------------

// acc = x (self-loop contribution), deg = 1 (self-loop)
__global__ void k_init(const float4* __restrict__ x4, int n) {
    int idx = blockIdx.x * blockDim.x + threadIdx.x;
    if (idx < n * 16) ((float4*)g_acc)[idx] = x4[idx];
    if (idx < n) g_deg[idx] = 1.0f;
}

// clusterGCN edge pass: acc[dst] += x[src]; deg[dst] += 1
__global__ void k_edge0(const int* __restrict__ src, const int* __restrict__ dst,
                        const float4* __restrict__ x4, int e) {
    int t = blockIdx.x * blockDim.x + threadIdx.x;
    int warp = t >> 5, lane = t & 31;
    int sub = lane >> 4, q = lane & 15;
    int ed = warp * 2 + sub;
    if (ed >= e) return;
    int s = src[ed], d = dst[ed];
    float4 v = x4[(size_t)s * 16 + q];
    red4(g_acc + (size_t)d * 64 + q * 4, v);
    if (q == 0) atomicAdd(&g_deg[d], 1.0f);
}

// h = relu(deg_inv*acc @ W_out + x @ W_root + b_out)
__global__ __launch_bounds__(128) void k_gemm0(
        const float* __restrict__ x, const float* __restrict__ Wout,
        const float* __restrict__ bout, const float* __restrict__ Wroot, int n) {
    __shared__ float sWo[4096], sWr[4096], sb[64];
    int tid = threadIdx.x;
    for (int i = tid; i < 4096; i += 128) { sWo[i] = Wout[i]; sWr[i] = Wroot[i]; }
    if (tid < 64) sb[tid] = bout[tid];
    __syncthreads();
    int node = blockIdx.x * 128 + tid;
    if (node >= n) return;
    float acc[64];
#pragma unroll
    for (int c = 0; c < 64; c++) acc[c] = 0.f;
    float dinv = 1.0f / g_deg[node];
    const float4* ar = (const float4*)(g_acc + (size_t)node * 64);
    const float4* xr = (const float4*)(x + (size_t)node * 64);
#pragma unroll 1
    for (int k4 = 0; k4 < 16; k4++) {
        float4 a = ar[k4];
        fma_row64(a.x * dinv, sWo + (k4*4+0)*64, acc);
        fma_row64(a.y * dinv, sWo + (k4*4+1)*64, acc);
        fma_row64(a.z * dinv, sWo + (k4*4+2)*64, acc);
        fma_row64(a.w * dinv, sWo + (k4*4+3)*64, acc);
    }
#pragma unroll 1
    for (int k4 = 0; k4 < 16; k4++) {
        float4 a = xr[k4];
        fma_row64(a.x, sWr + (k4*4+0)*64, acc);
        fma_row64(a.y, sWr + (k4*4+1)*64, acc);
        fma_row64(a.z, sWr + (k4*4+2)*64, acc);
        fma_row64(a.w, sWr + (k4*4+3)*64, acc);
    }
    float4* hr = (float4*)(g_h + (size_t)node * 64);
#pragma unroll
    for (int c4 = 0; c4 < 16; c4++) {
        float4 o;
        o.x = fmaxf(acc[c4*4+0] + sb[c4*4+0], 0.f);
        o.y = fmaxf(acc[c4*4+1] + sb[c4*4+1], 0.f);
        o.z = fmaxf(acc[c4*4+2] + sb[c4*4+2], 0.f);
        o.w = fmaxf(acc[c4*4+3] + sb[c4*4+3], 0.f);
        hr[c4] = o;
    }
}

// GAT1: h1 = h @ W1; s_src/s_dst; m init with self-loop logit
__global__ __launch_bounds__(128) void k_gemm_gat1(
        const float* __restrict__ W, const float* __restrict__ asv,
        const float* __restrict__ adv, int n) {
    __shared__ float sW[4096], sas[64], sad[64];
    int tid = threadIdx.x;
    for (int i = tid; i < 4096; i += 128) sW[i] = W[i];
    if (tid < 64) { sas[tid] = asv[tid]; sad[tid] = adv[tid]; }
    __syncthreads();
    int node = blockIdx.x * 128 + tid;
    if (node >= n) return;
    float acc[64];
#pragma unroll
    for (int c = 0; c < 64; c++) acc[c] = 0.f;
    const float4* hr = (const float4*)(g_h + (size_t)node * 64);
#pragma unroll 1
    for (int k4 = 0; k4 < 16; k4++) {
        float4 a = hr[k4];
        fma_row64(a.x, sW + (k4*4+0)*64, acc);
        fma_row64(a.y, sW + (k4*4+1)*64, acc);
        fma_row64(a.z, sW + (k4*4+2)*64, acc);
        fma_row64(a.w, sW + (k4*4+3)*64, acc);
    }
    float ss = 0.f, sd = 0.f;
#pragma unroll
    for (int c = 0; c < 64; c++) { ss = fmaf(acc[c], sas[c], ss); sd = fmaf(acc[c], sad[c], sd); }
    float4* o = (float4*)(g_h1 + (size_t)node * 64);
#pragma unroll
    for (int c4 = 0; c4 < 16; c4++)
        o[c4] = make_float4(acc[c4*4+0], acc[c4*4+1], acc[c4*4+2], acc[c4*4+3]);
    g_ssrc[node] = ss;
    g_sdst[node] = sd;
    g_menc[node] = fenc(lrelu(ss + sd));
}

// GAT2: in = relu(acc1/den1 + b1); h2 = in @ W2; s_src/s_dst; m init
__global__ __launch_bounds__(128) void k_gemm_gat2(
        const float* __restrict__ W, const float* __restrict__ asv,
        const float* __restrict__ adv, const float* __restrict__ b1, int n) {
    __shared__ float sW[2048], sas[32], sad[32], sb[64];
    int tid = threadIdx.x;
    for (int i = tid; i < 2048; i += 128) sW[i] = W[i];
    if (tid < 32) { sas[tid] = asv[tid]; sad[tid] = adv[tid]; }
    if (tid < 64) sb[tid] = b1[tid];
    __syncthreads();
    int node = blockIdx.x * 128 + tid;
    if (node >= n) return;
    float acc[32];
#pragma unroll
    for (int c = 0; c < 32; c++) acc[c] = 0.f;
    float rd = 1.0f / g_den[node];
    const float4* ar = (const float4*)(g_acc + (size_t)node * 64);
#pragma unroll 1
    for (int k4 = 0; k4 < 16; k4++) {
        float4 a = ar[k4];
        float i0 = fmaxf(fmaf(a.x, rd, sb[k4*4+0]), 0.f);
        float i1 = fmaxf(fmaf(a.y, rd, sb[k4*4+1]), 0.f);
        float i2 = fmaxf(fmaf(a.z, rd, sb[k4*4+2]), 0.f);
        float i3 = fmaxf(fmaf(a.w, rd, sb[k4*4+3]), 0.f);
        fma_row32(i0, sW + (k4*4+0)*32, acc);
        fma_row32(i1, sW + (k4*4+1)*32, acc);
        fma_row32(i2, sW + (k4*4+2)*32, acc);
        fma_row32(i3, sW + (k4*4+3)*32, acc);
    }
    float ss = 0.f, sd = 0.f;
#pragma unroll
    for (int c = 0; c < 32; c++) { ss = fmaf(acc[c], sas[c], ss); sd = fmaf(acc[c], sad[c], sd); }
    float4* o = (float4*)(g_h + (size_t)node * 32);
#pragma unroll
    for (int c4 = 0; c4 < 8; c4++)
        o[c4] = make_float4(acc[c4*4+0], acc[c4*4+1], acc[c4*4+2], acc[c4*4+3]);
    g_ssrc[node] = ss;
    g_sdst[node] = sd;
    g_menc[node] = fenc(lrelu(ss + sd));
}

// segment max of edge logits into m_enc (already seeded with self-loop logit)
__global__ void k_edge_max(const int* __restrict__ src, const int* __restrict__ dst, int e) {
    int t = blockIdx.x * blockDim.x + threadIdx.x;
    if (t >= e) return;
    int s = src[t], d = dst[t];
    unsigned key = fenc(lrelu(g_ssrc[s] + g_sdst[d]));
    atomicMax(&g_menc[d], key);
}

// decode m; init den and acc with self-loop term
template<int C>
__global__ void k_node_init(int n) {
    constexpr int L = C / 4;
    int idx = blockIdx.x * blockDim.x + threadIdx.x;
    if (idx >= n * L) return;
    int i = idx / L, q = idx % L;
    float mf = fdec(g_menc[i]);
    float ls = lrelu(g_ssrc[i] + g_sdst[i]);
    float ec = __expf(ls - mf);
    if (q == 0) { g_den[i] = ec; g_mf[i] = mf; }
    float4 v = ((const float4*)hbuf<C>())[(size_t)i * L + q];
    v.x *= ec; v.y *= ec; v.z *= ec; v.w *= ec;
    ((float4*)accbuf<C>())[(size_t)i * L + q] = v;
}

// unnormalized softmax-weighted aggregation: acc[dst] += e*h[src]; den[dst] += e
template<int C>
__global__ void k_edge_agg(const int* __restrict__ src, const int* __restrict__ dst, int e) {
    constexpr int L = C / 4, EPW = 32 / L;
    int t = blockIdx.x * blockDim.x + threadIdx.x;
    int warp = t >> 5, lane = t & 31;
    int sub = lane / L, q = lane % L;
    int ed = warp * EPW + sub;
    if (ed >= e) return;
    int s = src[ed], d = dst[ed];
    float ec = __expf(lrelu(g_ssrc[s] + g_sdst[d]) - g_mf[d]);
    float4 v = ((const float4*)hbuf<C>())[(size_t)s * L + q];
    v.x *= ec; v.y *= ec; v.z *= ec; v.w *= ec;
    red4(accbuf<C>() + (size_t)d * C + q * 4, v);
    if (q == 0) atomicAdd(&g_den[d], ec);
}

// out = acc2/den2 + b2
__global__ void k_final(float4* __restrict__ out4, const float* __restrict__ b2, int n) {
    int idx = blockIdx.x * blockDim.x + threadIdx.x;
    if (idx >= n * 8) return;
    int i = idx / 8, q = idx % 8;
    float rd = 1.0f / g_den[i];
    float4 v = ((const float4*)g_h1)[(size_t)i * 8 + q];
    float4 b = ((const float4*)b2)[q];
    out4[idx] = make_float4(fmaf(v.x, rd, b.x), fmaf(v.y, rd, b.y),
                            fmaf(v.z, rd, b.z), fmaf(v.w, rd, b.w));
}

// ---------------- launch ------------------------------------------------------
extern "C" void kernel_launch(void* const* d_in, const int* in_sizes, int n_in,
                              void* d_out, int out_size) {
    const float* x    = (const float*)d_in[0];
    const int*   ei   = (const int*)  d_in[1];
    const float* Wout = (const float*)d_in[2];
    const float* bout = (const float*)d_in[3];
    const float* Wroot= (const float*)d_in[4];
    const float* W1   = (const float*)d_in[5];
    const float* as1  = (const float*)d_in[6];
    const float* ad1  = (const float*)d_in[7];
    const float* b1   = (const float*)d_in[8];
    const float* W2   = (const float*)d_in[9];
    const float* as2  = (const float*)d_in[10];
    const float* ad2  = (const float*)d_in[11];
    const float* b2   = (const float*)d_in[12];

    int n = in_sizes[0] / 64;
    int e = in_sizes[1] / 2;
    const int* src = ei;
    const int* dst = ei + e;

    const int TB = 256;
    int nb_copy  = (n * 16 + TB - 1) / TB;   // n*16 float4 elems
    int nb_gemm  = (n + 127) / 128;
    int nb_e1    = (e + TB - 1) / TB;        // 1 thread / edge
    int nb_e16   = (e + 15) / 16;            // 16 edges / 256-thr block (16 lanes/edge)
    int nb_e32   = (e + 31) / 32;            // 32 edges / block (8 lanes/edge)
    int nb_n8    = (n * 8 + TB - 1) / TB;

    // Layer 0: ClusterGCN
    k_init <<<nb_copy, TB>>>((const float4*)x, n);
    k_edge0<<<nb_e16, TB>>>(src, dst, (const float4*)x, e);
    k_gemm0<<<nb_gemm, 128>>>(x, Wout, bout, Wroot, n);

    // Layer 1: GAT(64->64) + relu (relu fused into gat2 prologue)
    k_gemm_gat1<<<nb_gemm, 128>>>(W1, as1, ad1, n);
    k_edge_max <<<nb_e1, TB>>>(src, dst, e);
    k_node_init<64><<<nb_copy, TB>>>(n);
    k_edge_agg <64><<<nb_e16, TB>>>(src, dst, e);

    // Layer 2: GAT(64->32)
    k_gemm_gat2<<<nb_gemm, 128>>>(W2, as2, ad2, b1, n);
    k_edge_max <<<nb_e1, TB>>>(src, dst, e);
    k_node_init<32><<<nb_n8, TB>>>(n);
    k_edge_agg <32><<<nb_e32, TB>>>(src, dst, e);

    k_final<<<nb_n8, TB>>>((float4*)d_out, b2, n);
}